// round 5
// baseline (speedup 1.0000x reference)
#include <cuda_runtime.h>

#define NC 10000
#define NK 4
#define ND 2048
#define NP (NC * NK)                 // 40000 prototypes
#define RPB 32                       // rows per block = warps per block
#define BT  1024                     // block threads
#define GB  (NP / RPB)               // 1250 blocks
#define FLT_BIG 3.402823466e38f

// Scratch (device globals — allocation-free)
__device__ float        g_d[NP];          // squared distances (label rows read by finisher)
__device__ float2       g_part[GB];       // per-block (min_d, sum exp(min_d - d))
__device__ unsigned int g_counter = 0;    // completion counter; finisher resets to 0

// ---------------------------------------------------------------------------
// Fused kernel: one warp per prototype row -> block logsumexp partial ->
// last-done block combines all partials and writes the scalar output.
// ---------------------------------------------------------------------------
__global__ __launch_bounds__(BT)
void fused_kernel(const float* __restrict__ proto, const float* __restrict__ feat,
                  const int* __restrict__ label_p, float* __restrict__ out) {
    __shared__ float4 sf4[ND / 4];      // 8 KB feature cache
    __shared__ float  sd[RPB];          // per-warp row distances
    __shared__ float  sred[32];
    __shared__ float  s_min;
    __shared__ int    s_last;

    const int tid  = threadIdx.x;
    const int warp = tid >> 5;
    const int lane = tid & 31;

    // stage feature into smem
    const float4* __restrict__ f4 = reinterpret_cast<const float4*>(feat);
#pragma unroll
    for (int i = tid; i < ND / 4; i += BT) sf4[i] = f4[i];
    __syncthreads();

    // ---- phase 1: squared distance for this warp's row (streaming loads) ----
    const int row = blockIdx.x * RPB + warp;
    const float4* __restrict__ p4 =
        reinterpret_cast<const float4*>(proto + (size_t)row * ND);

    float acc = 0.0f;
#pragma unroll
    for (int it = 0; it < (ND / 4) / 32; it++) {   // 16 independent float4 loads
        const int idx = it * 32 + lane;
        float4 p = __ldcs(p4 + idx);               // single-use: evict-first
        float4 f = sf4[idx];
        float d0 = p.x - f.x;
        float d1 = p.y - f.y;
        float d2 = p.z - f.z;
        float d3 = p.w - f.w;
        acc += d0 * d0 + d1 * d1 + d2 * d2 + d3 * d3;
    }

#pragma unroll
    for (int o = 16; o > 0; o >>= 1)
        acc += __shfl_xor_sync(0xFFFFFFFFu, acc, o);

    if (lane == 0) {
        g_d[row] = acc;
        sd[warp] = acc;
    }
    __syncthreads();

    // ---- phase 2: block logsumexp partial over 32 row distances (warp 0) ----
    if (warp == 0) {
        float d = sd[lane];
        float m = d;
#pragma unroll
        for (int o = 16; o > 0; o >>= 1)
            m = fminf(m, __shfl_xor_sync(0xFFFFFFFFu, m, o));
        float e = expf(m - d);                     // exp(-(d - m)) in (0, 1]
#pragma unroll
        for (int o = 16; o > 0; o >>= 1)
            e += __shfl_xor_sync(0xFFFFFFFFu, e, o);
        if (lane == 0) g_part[blockIdx.x] = make_float2(m, e);
    }

    // ---- completion protocol: last block to finish becomes the finisher ----
    if (tid == 0) {
        __threadfence();                           // publish g_d / g_part
        unsigned int prev = atomicAdd(&g_counter, 1u);
        s_last = (prev == GB - 1u);
    }
    __syncthreads();
    if (!s_last) return;

    // =======================================================================
    // Finisher: combine 1250 partials (10 KB, L2-hot) and emit the scalar.
    //   m* = min_b m_b;  one = sum_b s_b * exp(m* - m_b)
    //   prob = sum_k ( -m* + log(one) + d[label*K + k] )
    // =======================================================================
    float  m0 = FLT_BIG, m1 = FLT_BIG;
    float2 p0 = make_float2(0.f, 0.f), p1 = make_float2(0.f, 0.f);
    if (tid < GB)      { p0 = g_part[tid];      m0 = p0.x; }
    if (tid + BT < GB) { p1 = g_part[tid + BT]; m1 = p1.x; }

    // global min of m_b
    float mn = fminf(m0, m1);
#pragma unroll
    for (int o = 16; o > 0; o >>= 1)
        mn = fminf(mn, __shfl_xor_sync(0xFFFFFFFFu, mn, o));
    if (lane == 0) sred[warp] = mn;
    __syncthreads();
    if (warp == 0) {
        float v = sred[lane];
#pragma unroll
        for (int o = 16; o > 0; o >>= 1)
            v = fminf(v, __shfl_xor_sync(0xFFFFFFFFu, v, o));
        if (lane == 0) s_min = v;
    }
    __syncthreads();
    const float mstar = s_min;

    // combine sums
    float s = 0.0f;
    if (tid < GB)      s += p0.y * expf(mstar - p0.x);
    if (tid + BT < GB) s += p1.y * expf(mstar - p1.x);
#pragma unroll
    for (int o = 16; o > 0; o >>= 1)
        s += __shfl_xor_sync(0xFFFFFFFFu, s, o);
    if (lane == 0) sred[warp] = s;
    __syncthreads();

    if (tid == 0) {
        float tot = 0.0f;
#pragma unroll
        for (int w = 0; w < 32; w++) tot += sred[w];
        const float log_one = -mstar + logf(tot);
        const int   label   = *label_p;
        float prob = 0.0f;
#pragma unroll
        for (int k = 0; k < NK; k++)
            prob += log_one + g_d[label * NK + k];
        out[0] = prob;
        g_counter = 0;                             // reset for next graph replay
    }
}

// ---------------------------------------------------------------------------
// Inputs (metadata order): feature [2048 f32], label [1 i32],
// all_prototypes [10000*4*2048 f32]. Output: 1 f32.
// ---------------------------------------------------------------------------
extern "C" void kernel_launch(void* const* d_in, const int* in_sizes, int n_in,
                              void* d_out, int out_size) {
    const float* feat  = (const float*)d_in[0];
    const int*   label = (const int*)d_in[1];
    const float* proto = (const float*)d_in[2];
    float*       out   = (float*)d_out;

    fused_kernel<<<GB, BT>>>(proto, feat, label, out);
}